// round 5
// baseline (speedup 1.0000x reference)
#include <cuda_runtime.h>

// Problem constants
#define BB 8
#define NN 4096
#define KK 26
#define DD 64

// Stage-1 tiling
#define NCHUNK 64                 // n-chunks per batch
#define CHUNK_N (NN / NCHUNK)     // 64 n's per block
#define KD (KK * DD)              // 1664

// Deterministic partial-sum scratch: 2 x [B][NCHUNK][K][D] = 6.8 MB total
__device__ float g_part1[BB * NCHUNK * KD];   // sum (tt*a)*nb
__device__ float g_part2[BB * NCHUNK * KD];   // sum (tt*a)

__device__ __forceinline__ float4 f4_fma(float4 x, float4 m, float4 b) {
    float4 r;
    r.x = fmaf(x.x, m.x, b.x);
    r.y = fmaf(x.y, m.y, b.y);
    r.z = fmaf(x.z, m.z, b.z);
    r.w = fmaf(x.w, m.w, b.w);
    return r;
}

__device__ __forceinline__ float4 f4_scale(float4 x, float s) {
    float4 r; r.x = x.x * s; r.y = x.y * s; r.z = x.z * s; r.w = x.w * s;
    return r;
}

__device__ __forceinline__ void f4_fma_acc(float4& acc, float4 u, float4 v) {
    acc.x = fmaf(u.x, v.x, acc.x);
    acc.y = fmaf(u.y, v.y, acc.y);
    acc.z = fmaf(u.z, v.z, acc.z);
    acc.w = fmaf(u.w, v.w, acc.w);
}

__device__ __forceinline__ void f4_add(float4& acc, float4 u) {
    acc.x += u.x; acc.y += u.y; acc.z += u.z; acc.w += u.w;
}

// Stage 1: 416 threads = 26 k-lanes x 16 d4-lanes, one k-slot per thread.
// acc1 += (tt*a) * nb ; acc2 += (tt*a).  kt/bt applied in stage2 via linearity:
//   sum_n (tt*a)*(nb*kt+bt) = kt * sum_n (tt*a)*nb + bt * sum_n (tt*a)
__global__ void __launch_bounds__(416, 3) gat_stage1(
    const float* __restrict__ targets,     // (B,N,D)
    const float* __restrict__ neighbors,   // (B,N,K,D)
    const float* __restrict__ aw,          // (B,N,K)
    const float* __restrict__ kn,          // kernel_neighbor (D)
    const float* __restrict__ bn)          // bias_neighbor   (D)
{
    const int chunk = blockIdx.x;          // 0..NCHUNK-1
    const int b     = blockIdx.y;          // 0..B-1
    const int tid   = threadIdx.x;
    const int d4    = tid & 15;
    const int kl    = tid >> 4;            // 0..25

    // Loop-invariant per-d constants (8 regs)
    const float4 kn4 = ((const float4*)kn)[d4];
    const float4 bn4 = ((const float4*)bn)[d4];

    float4 acc1 = make_float4(0.f, 0.f, 0.f, 0.f);
    float4 acc2 = make_float4(0.f, 0.f, 0.f, 0.f);

    const long n0   = (long)chunk * CHUNK_N;
    const long row0 = (long)b * NN + n0;

    const float* tg_base = targets   + row0 * DD;
    const float* nb_base = neighbors + row0 * (long)KD + kl * DD;
    const float* aw_base = aw        + row0 * KK + kl;

    #pragma unroll 4
    for (int i = 0; i < CHUNK_N; i++) {
        float4 tg = ((const float4*)(tg_base + (long)i * DD))[d4];
        float  a0 = __ldg(aw_base + (long)i * KK);
        float4 nb = ((const float4*)(nb_base + (long)i * KD))[d4];

        float4 tt = f4_fma(tg, kn4, bn4);      // targets*kn + bn
        float4 ta = f4_scale(tt, a0);          // (tt*a)
        f4_fma_acc(acc1, ta, nb);              // acc1 += ta*nb
        f4_add(acc2, ta);                      // acc2 += ta
    }

    const long outoff = ((long)(b * NCHUNK + chunk)) * KD + kl * DD;
    ((float4*)(g_part1 + outoff))[d4] = acc1;
    ((float4*)(g_part2 + outoff))[d4] = acc2;
}

// Stage 2: one block per (b,k). 512 threads = 16 d4-lanes x 32 chunk-groups.
// Each thread sums 2 chunks of each partial array (4 independent LDG.128),
// smem combine, w = kt*S1 + bt*S2, sigmoid, float4 store.
__global__ void __launch_bounds__(512) gat_stage2(
    float* __restrict__ out,
    const float* __restrict__ kt,
    const float* __restrict__ bt)
{
    __shared__ float4 red1[32][16];
    __shared__ float4 red2[32][16];

    const int k = blockIdx.x;              // 0..KK-1
    const int b = blockIdx.y;              // 0..BB-1
    const int tid = threadIdx.x;
    const int d4 = tid & 15;
    const int g  = tid >> 4;               // 0..31

    const long cstride = (long)KD;         // per-chunk stride in floats
    const long base = ((long)(b * NCHUNK) * KK + k) * DD;

    const long off0 = base + (long)(2 * g)     * cstride + d4 * 4;
    const long off1 = base + (long)(2 * g + 1) * cstride + d4 * 4;

    float4 s1 = *(const float4*)(g_part1 + off0);
    float4 t1 = *(const float4*)(g_part1 + off1);
    float4 s2 = *(const float4*)(g_part2 + off0);
    float4 t2 = *(const float4*)(g_part2 + off1);
    f4_add(s1, t1);
    f4_add(s2, t2);

    red1[g][d4] = s1;
    red2[g][d4] = s2;
    __syncthreads();

    if (tid < 16) {
        float4 S1 = make_float4(0.f, 0.f, 0.f, 0.f);
        float4 S2 = make_float4(0.f, 0.f, 0.f, 0.f);
        #pragma unroll
        for (int gg = 0; gg < 32; gg++) {
            f4_add(S1, red1[gg][d4]);
            f4_add(S2, red2[gg][d4]);
        }
        float4 kt4 = ((const float4*)kt)[d4];
        float4 bt4 = ((const float4*)bt)[d4];
        float4 w;
        w.x = fmaf(kt4.x, S1.x, bt4.x * S2.x);
        w.y = fmaf(kt4.y, S1.y, bt4.y * S2.y);
        w.z = fmaf(kt4.z, S1.z, bt4.z * S2.z);
        w.w = fmaf(kt4.w, S1.w, bt4.w * S2.w);

        float4 r;
        r.x = 1.0f / (1.0f + __expf(-w.x));
        r.y = 1.0f / (1.0f + __expf(-w.y));
        r.z = 1.0f / (1.0f + __expf(-w.z));
        r.w = 1.0f / (1.0f + __expf(-w.w));

        ((float4*)(out + ((long)b * KK + k) * DD))[d4] = r;
    }
}

extern "C" void kernel_launch(void* const* d_in, const int* in_sizes, int n_in,
                              void* d_out, int out_size)
{
    const float* targets   = (const float*)d_in[0];  // (B,N,D)
    const float* neighbors = (const float*)d_in[1];  // (B,N,K,D)
    const float* aw        = (const float*)d_in[2];  // (B,N,K)
    const float* kt        = (const float*)d_in[3];  // kernel_target
    const float* bt        = (const float*)d_in[4];  // bias_target
    const float* kn        = (const float*)d_in[5];  // kernel_neighbor
    const float* bn        = (const float*)d_in[6];  // bias_neighbor
    float* out             = (float*)d_out;          // (1,B,K,D)

    (void)in_sizes; (void)n_in; (void)out_size;

    dim3 g1(NCHUNK, BB);
    gat_stage1<<<g1, 416>>>(targets, neighbors, aw, kn, bn);

    dim3 g2(KK, BB);
    gat_stage2<<<g2, 512>>>(out, kt, bt);
}

// round 6
// speedup vs baseline: 1.2292x; 1.2292x over previous
#include <cuda_runtime.h>

// Problem constants
#define BB 8
#define NN 4096
#define KK 26
#define DD 64

// Stage-1 tiling
#define NCHUNK 64                 // n-chunks per batch
#define CHUNK_N (NN / NCHUNK)     // 64 n's per block
#define KD (KK * DD)              // 1664

// Deterministic partial-sum scratch: [B][NCHUNK][K][D] = 3.4 MB
__device__ float g_partial[BB * NCHUNK * KD];

__device__ __forceinline__ float4 f4_fma(float4 x, float4 m, float4 b) {
    float4 r;
    r.x = fmaf(x.x, m.x, b.x);
    r.y = fmaf(x.y, m.y, b.y);
    r.z = fmaf(x.z, m.z, b.z);
    r.w = fmaf(x.w, m.w, b.w);
    return r;
}

__device__ __forceinline__ float4 f4_scale(float4 x, float s) {
    float4 r; r.x = x.x * s; r.y = x.y * s; r.z = x.z * s; r.w = x.w * s;
    return r;
}

// acc += u * v
__device__ __forceinline__ void f4_fma_acc(float4& acc, float4 u, float4 v) {
    acc.x = fmaf(u.x, v.x, acc.x);
    acc.y = fmaf(u.y, v.y, acc.y);
    acc.z = fmaf(u.z, v.z, acc.z);
    acc.w = fmaf(u.w, v.w, acc.w);
}

// Stage 1 (R1 config — 512 blocks x 256 thr, occ 4 => single wave):
// Thread map: d4 = tid & 15 (float4 group over D=64), kl = tid >> 4 (0..15).
// Each thread owns k = kl and k = kl + 16 (second valid only for kl < 10).
__global__ void __launch_bounds__(256, 4) gat_stage1(
    const float* __restrict__ targets,     // (B,N,D)
    const float* __restrict__ neighbors,   // (B,N,K,D)
    const float* __restrict__ aw,          // (B,N,K)
    const float* __restrict__ kt,          // kernel_target (D)
    const float* __restrict__ bt,          // bias_target   (D)
    const float* __restrict__ kn,          // kernel_neighbor (D)
    const float* __restrict__ bn)          // bias_neighbor   (D)
{
    const int chunk = blockIdx.x;          // 0..NCHUNK-1
    const int b     = blockIdx.y;          // 0..B-1
    const int tid   = threadIdx.x;
    const int d4    = tid & 15;
    const int kl    = tid >> 4;
    const bool has_k1 = (kl + 16) < KK;    // kl < 10

    // Loop-invariant per-d constants
    const float4 kt4 = ((const float4*)kt)[d4];
    const float4 bt4 = ((const float4*)bt)[d4];
    const float4 kn4 = ((const float4*)kn)[d4];
    const float4 bn4 = ((const float4*)bn)[d4];

    float4 acc0 = make_float4(0.f, 0.f, 0.f, 0.f);
    float4 acc1 = make_float4(0.f, 0.f, 0.f, 0.f);

    const long n0 = (long)chunk * CHUNK_N;
    const long row0 = (long)b * NN + n0;

    const float* tg_base = targets   + row0 * DD;
    const float* nb_base = neighbors + row0 * (long)KD;
    const float* aw_base = aw        + row0 * KK;

    #pragma unroll 4
    for (int i = 0; i < CHUNK_N; i++) {
        // t[b,n,:] = targets * kernel_neighbor + bias_neighbor
        float4 tg = ((const float4*)(tg_base + (long)i * DD))[d4];
        float4 tt = f4_fma(tg, kn4, bn4);

        const float* nrow = nb_base + (long)i * KD;
        const float* arow = aw_base + (long)i * KK;

        // k = kl
        {
            float a0 = __ldg(arow + kl);
            float4 nb = ((const float4*)(nrow + kl * DD))[d4];
            float4 nv = f4_fma(nb, kt4, bt4);        // neighbors*kt + bt
            f4_fma_acc(acc0, nv, f4_scale(tt, a0));  // acc += nv * (tt*a)
        }
        // k = kl + 16
        if (has_k1) {
            float a1 = __ldg(arow + kl + 16);
            float4 nb = ((const float4*)(nrow + (kl + 16) * DD))[d4];
            float4 nv = f4_fma(nb, kt4, bt4);
            f4_fma_acc(acc1, nv, f4_scale(tt, a1));
        }
    }

    float* outp = g_partial + ((long)(b * NCHUNK + chunk)) * KD;
    ((float4*)(outp + kl * DD))[d4] = acc0;
    if (has_k1) ((float4*)(outp + (kl + 16) * DD))[d4] = acc1;
}

// Stage 2 (R2 config — best measured): one block per (b,k).
// 256 threads = 64 d-lanes x 4 chunk-groups; each thread sums 16 chunks
// (independent strided loads, MLP=16), smem combine, sigmoid.
__global__ void __launch_bounds__(256) gat_stage2(float* __restrict__ out)
{
    __shared__ float red[4][DD];

    const int k = blockIdx.x;              // 0..KK-1
    const int b = blockIdx.y;              // 0..BB-1
    const int tid = threadIdx.x;
    const int d = tid & (DD - 1);
    const int g = tid >> 6;                // 0..3

    // g_partial[((b*NCHUNK + c)*KK + k)*DD + d]
    const float* base = g_partial + ((long)(b * NCHUNK) * KK + k) * DD + d;
    const long cstride = (long)KK * DD;    // per-chunk stride

    float s = 0.f;
    #pragma unroll
    for (int j = 0; j < NCHUNK / 4; j++) {  // 16 chunks per group
        int c = g * (NCHUNK / 4) + j;
        s += base[(long)c * cstride];
    }
    red[g][d] = s;
    __syncthreads();

    if (tid < DD) {
        float t = red[0][d] + red[1][d] + red[2][d] + red[3][d];
        float r = 1.0f / (1.0f + __expf(-t));
        out[((long)b * KK + k) * DD + d] = r;
    }
}

extern "C" void kernel_launch(void* const* d_in, const int* in_sizes, int n_in,
                              void* d_out, int out_size)
{
    const float* targets   = (const float*)d_in[0];  // (B,N,D)
    const float* neighbors = (const float*)d_in[1];  // (B,N,K,D)
    const float* aw        = (const float*)d_in[2];  // (B,N,K)
    const float* kt        = (const float*)d_in[3];  // kernel_target
    const float* bt        = (const float*)d_in[4];  // bias_target
    const float* kn        = (const float*)d_in[5];  // kernel_neighbor
    const float* bn        = (const float*)d_in[6];  // bias_neighbor
    float* out             = (float*)d_out;          // (1,B,K,D)

    (void)in_sizes; (void)n_in; (void)out_size;

    dim3 g1(NCHUNK, BB);
    gat_stage1<<<g1, 256>>>(targets, neighbors, aw, kt, bt, kn, bn);

    dim3 g2(KK, BB);
    gat_stage2<<<g2, 256>>>(out);
}

// round 8
// speedup vs baseline: 1.2314x; 1.0018x over previous
#include <cuda_runtime.h>

// Problem constants
#define BB 8
#define NN 4096
#define KK 26
#define DD 64

// Stage-1 tiling: 74 chunks/batch * 8 batches = 592 blocks = 148 SMs * occ 4
// => perfectly balanced single wave (every SM runs exactly 4 blocks).
#define NCHUNK 74
#define KD (KK * DD)              // 1664

// Deterministic partial-sum scratch: [B][NCHUNK][K][D] = ~3.9 MB
__device__ float g_partial[BB * NCHUNK * KD];

__device__ __forceinline__ float4 f4_fma(float4 x, float4 m, float4 b) {
    float4 r;
    r.x = fmaf(x.x, m.x, b.x);
    r.y = fmaf(x.y, m.y, b.y);
    r.z = fmaf(x.z, m.z, b.z);
    r.w = fmaf(x.w, m.w, b.w);
    return r;
}

__device__ __forceinline__ float4 f4_scale(float4 x, float s) {
    float4 r; r.x = x.x * s; r.y = x.y * s; r.z = x.z * s; r.w = x.w * s;
    return r;
}

// acc += u * v
__device__ __forceinline__ void f4_fma_acc(float4& acc, float4 u, float4 v) {
    acc.x = fmaf(u.x, v.x, acc.x);
    acc.y = fmaf(u.y, v.y, acc.y);
    acc.z = fmaf(u.z, v.z, acc.z);
    acc.w = fmaf(u.w, v.w, acc.w);
}

__device__ __forceinline__ void f4_add(float4& acc, float4 u) {
    acc.x += u.x; acc.y += u.y; acc.z += u.z; acc.w += u.w;
}

// Stage 1: thread map d4 = tid & 15 (float4 over D=64), kl = tid >> 4 (0..15).
// Each thread owns k = kl and k = kl + 16 (second valid only for kl < 10).
// Block handles n in [chunk*NN/74, (chunk+1)*NN/74)  (55 or 56 rows).
__global__ void __launch_bounds__(256, 4) gat_stage1(
    const float* __restrict__ targets,     // (B,N,D)
    const float* __restrict__ neighbors,   // (B,N,K,D)
    const float* __restrict__ aw,          // (B,N,K)
    const float* __restrict__ kt,          // kernel_target (D)
    const float* __restrict__ bt,          // bias_target   (D)
    const float* __restrict__ kn,          // kernel_neighbor (D)
    const float* __restrict__ bn)          // bias_neighbor   (D)
{
    const int chunk = blockIdx.x;          // 0..NCHUNK-1
    const int b     = blockIdx.y;          // 0..B-1
    const int tid   = threadIdx.x;
    const int d4    = tid & 15;
    const int kl    = tid >> 4;
    const bool has_k1 = (kl + 16) < KK;    // kl < 10

    // Loop-invariant per-d constants
    const float4 kt4 = ((const float4*)kt)[d4];
    const float4 bt4 = ((const float4*)bt)[d4];
    const float4 kn4 = ((const float4*)kn)[d4];
    const float4 bn4 = ((const float4*)bn)[d4];

    float4 acc0 = make_float4(0.f, 0.f, 0.f, 0.f);
    float4 acc1 = make_float4(0.f, 0.f, 0.f, 0.f);

    const int n_start = (chunk * NN) / NCHUNK;
    const int n_end   = ((chunk + 1) * NN) / NCHUNK;
    const int count   = n_end - n_start;

    const long row0 = (long)b * NN + n_start;

    const float* tg_base = targets   + row0 * DD;
    const float* nb_base = neighbors + row0 * (long)KD;
    const float* aw_base = aw        + row0 * KK;

    #pragma unroll 4
    for (int i = 0; i < count; i++) {
        // t[b,n,:] = targets * kernel_neighbor + bias_neighbor
        float4 tg = ((const float4*)(tg_base + (long)i * DD))[d4];
        float4 tt = f4_fma(tg, kn4, bn4);

        const float* nrow = nb_base + (long)i * KD;
        const float* arow = aw_base + (long)i * KK;

        // k = kl
        {
            float a0 = __ldg(arow + kl);
            float4 nb = ((const float4*)(nrow + kl * DD))[d4];
            float4 nv = f4_fma(nb, kt4, bt4);        // neighbors*kt + bt
            f4_fma_acc(acc0, nv, f4_scale(tt, a0));  // acc += nv * (tt*a)
        }
        // k = kl + 16
        if (has_k1) {
            float a1 = __ldg(arow + kl + 16);
            float4 nb = ((const float4*)(nrow + (kl + 16) * DD))[d4];
            float4 nv = f4_fma(nb, kt4, bt4);
            f4_fma_acc(acc1, nv, f4_scale(tt, a1));
        }
    }

    float* outp = g_partial + ((long)(b * NCHUNK + chunk)) * KD;
    ((float4*)(outp + kl * DD))[d4] = acc0;
    if (has_k1) ((float4*)(outp + (kl + 16) * DD))[d4] = acc1;
}

// Stage 2: one block per (b,k). 256 threads = 16 d4-lanes x 16 groups.
// Group g sums chunks {g, g+16, g+32, g+48, g+64(<74)} with float4 loads
// (4-5 independent LDG.128 per thread), smem combine, sigmoid, f4 store.
__global__ void __launch_bounds__(256) gat_stage2(float* __restrict__ out)
{
    __shared__ float4 red[16][16];

    const int k = blockIdx.x;              // 0..KK-1
    const int b = blockIdx.y;              // 0..BB-1
    const int tid = threadIdx.x;
    const int d4 = tid & 15;
    const int g  = tid >> 4;               // 0..15

    // element base: g_partial[((b*NCHUNK + c)*KK + k)*DD + d4*4]
    const float* base = g_partial + ((long)(b * NCHUNK) * KK + k) * DD + d4 * 4;
    const long cstride = (long)KD;         // per-chunk stride in floats

    float4 s = make_float4(0.f, 0.f, 0.f, 0.f);
    #pragma unroll
    for (int j = 0; j < 5; j++) {
        int c = g + j * 16;
        if (c < NCHUNK) {
            float4 v = *(const float4*)(base + (long)c * cstride);
            f4_add(s, v);
        }
    }
    red[g][d4] = s;
    __syncthreads();

    if (tid < 16) {
        float4 S = make_float4(0.f, 0.f, 0.f, 0.f);
        #pragma unroll
        for (int gg = 0; gg < 16; gg++) f4_add(S, red[gg][d4]);

        float4 r;
        r.x = 1.0f / (1.0f + __expf(-S.x));
        r.y = 1.0f / (1.0f + __expf(-S.y));
        r.z = 1.0f / (1.0f + __expf(-S.z));
        r.w = 1.0f / (1.0f + __expf(-S.w));

        ((float4*)(out + ((long)b * KK + k) * DD))[d4] = r;
    }
}

extern "C" void kernel_launch(void* const* d_in, const int* in_sizes, int n_in,
                              void* d_out, int out_size)
{
    const float* targets   = (const float*)d_in[0];  // (B,N,D)
    const float* neighbors = (const float*)d_in[1];  // (B,N,K,D)
    const float* aw        = (const float*)d_in[2];  // (B,N,K)
    const float* kt        = (const float*)d_in[3];  // kernel_target
    const float* bt        = (const float*)d_in[4];  // bias_target
    const float* kn        = (const float*)d_in[5];  // kernel_neighbor
    const float* bn        = (const float*)d_in[6];  // bias_neighbor
    float* out             = (float*)d_out;          // (1,B,K,D)

    (void)in_sizes; (void)n_in; (void)out_size;

    dim3 g1(NCHUNK, BB);
    gat_stage1<<<g1, 256>>>(targets, neighbors, aw, kt, bt, kn, bn);

    dim3 g2(KK, BB);
    gat_stage2<<<g2, 256>>>(out);
}

// round 9
// speedup vs baseline: 1.2814x; 1.0407x over previous
#include <cuda_runtime.h>
#include <cstdint>

// Problem constants
#define BB 8
#define NN 4096
#define KK 26
#define DD 64

// Stage-1 tiling: 74 chunks/batch * 8 batches = 592 blocks = 148 SMs * occ 4
#define NCHUNK 74
#define KD (KK * DD)               // 1664 floats per n-row of neighbors
#define ROW_BYTES (KD * 4)         // 6656 B
#define TGROW_BYTES (DD * 4)       // 256 B

// Async-pipeline config
#define STAGES 3
#define RPS 2                               // rows per stage
#define NB_STAGE_BYTES (RPS * ROW_BYTES)    // 13312
#define TG_STAGE_BYTES (RPS * TGROW_BYTES)  // 512
#define STAGE_BYTES (NB_STAGE_BYTES + TG_STAGE_BYTES)  // 13824
#define SMEM_DATA (STAGES * STAGE_BYTES)    // 41472

// Deterministic partial-sum scratch: [B][NCHUNK][K][D] = ~3.9 MB
__device__ float g_partial[BB * NCHUNK * KD];

__device__ __forceinline__ float4 f4_fma(float4 x, float4 m, float4 b) {
    float4 r;
    r.x = fmaf(x.x, m.x, b.x);
    r.y = fmaf(x.y, m.y, b.y);
    r.z = fmaf(x.z, m.z, b.z);
    r.w = fmaf(x.w, m.w, b.w);
    return r;
}
__device__ __forceinline__ float4 f4_scale(float4 x, float s) {
    float4 r; r.x = x.x * s; r.y = x.y * s; r.z = x.z * s; r.w = x.w * s;
    return r;
}
__device__ __forceinline__ void f4_fma_acc(float4& acc, float4 u, float4 v) {
    acc.x = fmaf(u.x, v.x, acc.x);
    acc.y = fmaf(u.y, v.y, acc.y);
    acc.z = fmaf(u.z, v.z, acc.z);
    acc.w = fmaf(u.w, v.w, acc.w);
}
__device__ __forceinline__ void f4_add(float4& acc, float4 u) {
    acc.x += u.x; acc.y += u.y; acc.z += u.z; acc.w += u.w;
}

__device__ __forceinline__ uint32_t smem_u32(const void* p) {
    uint32_t a;
    asm("{ .reg .u64 t; cvta.to.shared.u64 t, %1; cvt.u32.u64 %0, t; }"
        : "=r"(a) : "l"(p));
    return a;
}
__device__ __forceinline__ void mbar_init(uint32_t mbar, uint32_t count) {
    asm volatile("mbarrier.init.shared.b64 [%0], %1;" :: "r"(mbar), "r"(count) : "memory");
}
__device__ __forceinline__ void mbar_expect_tx(uint32_t mbar, uint32_t bytes) {
    asm volatile("mbarrier.arrive.expect_tx.shared.b64 _, [%0], %1;"
                 :: "r"(mbar), "r"(bytes) : "memory");
}
__device__ __forceinline__ void mbar_wait(uint32_t mbar, uint32_t parity) {
    asm volatile(
        "{\n\t"
        ".reg .pred P;\n\t"
        "WAIT_%=:\n\t"
        "mbarrier.try_wait.parity.acquire.cta.shared::cta.b64 P, [%0], %1, 0x989680;\n\t"
        "@!P bra WAIT_%=;\n\t"
        "}"
        :: "r"(mbar), "r"(parity) : "memory");
}
__device__ __forceinline__ void bulk_g2s(uint32_t dst, const void* src,
                                         uint32_t bytes, uint32_t mbar) {
    asm volatile(
        "cp.async.bulk.shared::cta.global.mbarrier::complete_tx::bytes [%0], [%1], %2, [%3];"
        :: "r"(dst), "l"(src), "r"(bytes), "r"(mbar) : "memory");
}

// Stage 1: async-bulk pipelined streaming.
// 256 threads = 16 d4-lanes x 16 kl-lanes; thread owns k=kl (and kl+16 if <26).
__global__ void __launch_bounds__(256, 4) gat_stage1(
    const float* __restrict__ targets,     // (B,N,D)
    const float* __restrict__ neighbors,   // (B,N,K,D)
    const float* __restrict__ aw,          // (B,N,K)
    const float* __restrict__ kt,          // kernel_target (D)
    const float* __restrict__ bt,          // bias_target   (D)
    const float* __restrict__ kn,          // kernel_neighbor (D)
    const float* __restrict__ bn)          // bias_neighbor   (D)
{
    __shared__ __align__(128) unsigned char smem[SMEM_DATA + STAGES * 8];

    const int chunk = blockIdx.x;          // 0..NCHUNK-1
    const int b     = blockIdx.y;          // 0..B-1
    const int tid   = threadIdx.x;
    const int d4    = tid & 15;
    const int kl    = tid >> 4;
    const bool has_k1 = (kl + 16) < KK;    // kl < 10

    const float4 kt4 = ((const float4*)kt)[d4];
    const float4 bt4 = ((const float4*)bt)[d4];
    const float4 kn4 = ((const float4*)kn)[d4];
    const float4 bn4 = ((const float4*)bn)[d4];

    float4 acc0 = make_float4(0.f, 0.f, 0.f, 0.f);
    float4 acc1 = make_float4(0.f, 0.f, 0.f, 0.f);

    const int n_start = (chunk * NN) / NCHUNK;
    const int n_end   = ((chunk + 1) * NN) / NCHUNK;
    const int count   = n_end - n_start;           // 55 or 56
    const int nstg    = (count + RPS - 1) / RPS;

    const long row0 = (long)b * NN + n_start;
    const float* nb_g = neighbors + row0 * (long)KD;
    const float* tg_g = targets   + row0 * DD;
    const float* aw_base = aw + row0 * KK + kl;

    const uint32_t sbase = smem_u32(smem);
    const uint32_t mbar0 = sbase + SMEM_DATA;

    if (tid == 0) {
        #pragma unroll
        for (int s = 0; s < STAGES; s++) mbar_init(mbar0 + s * 8, 1);
    }
    __syncthreads();

    // Prologue: fill the pipeline
    if (tid == 0) {
        #pragma unroll
        for (int i = 0; i < STAGES; i++) {
            if (i < nstg) {
                int st = i;
                int rows = min(RPS, count - i * RPS);
                uint32_t nbb = rows * ROW_BYTES;
                uint32_t tgb = rows * TGROW_BYTES;
                uint32_t mb = mbar0 + st * 8;
                mbar_expect_tx(mb, nbb + tgb);
                bulk_g2s(sbase + st * STAGE_BYTES, nb_g + (long)i * RPS * KD, nbb, mb);
                bulk_g2s(sbase + st * STAGE_BYTES + NB_STAGE_BYTES,
                         tg_g + (long)i * RPS * DD, tgb, mb);
            }
        }
    }

    for (int i = 0; i < nstg; i++) {
        const int st = i % STAGES;
        const uint32_t parity = (uint32_t)((i / STAGES) & 1);
        mbar_wait(mbar0 + st * 8, parity);

        const int rows = min(RPS, count - i * RPS);
        const unsigned char* stg = smem + st * STAGE_BYTES;

        #pragma unroll
        for (int r = 0; r < RPS; r++) {
            if (r < rows) {
                const int n = i * RPS + r;
                float4 tg = ((const float4*)(stg + NB_STAGE_BYTES + r * TGROW_BYTES))[d4];
                float4 tt = f4_fma(tg, kn4, bn4);

                float a0 = __ldg(aw_base + (long)n * KK);
                float4 nb0 = ((const float4*)(stg + r * ROW_BYTES + kl * DD * 4))[d4];
                float4 nv0 = f4_fma(nb0, kt4, bt4);
                f4_fma_acc(acc0, nv0, f4_scale(tt, a0));

                if (has_k1) {
                    float a1 = __ldg(aw_base + (long)n * KK + 16);
                    float4 nb1 = ((const float4*)(stg + r * ROW_BYTES + (kl + 16) * DD * 4))[d4];
                    float4 nv1 = f4_fma(nb1, kt4, bt4);
                    f4_fma_acc(acc1, nv1, f4_scale(tt, a1));
                }
            }
        }
        __syncthreads();   // all threads done with stage st

        if (tid == 0 && (i + STAGES) < nstg) {
            int j = i + STAGES;
            int rows2 = min(RPS, count - j * RPS);
            uint32_t nbb = rows2 * ROW_BYTES;
            uint32_t tgb = rows2 * TGROW_BYTES;
            uint32_t mb = mbar0 + st * 8;
            mbar_expect_tx(mb, nbb + tgb);
            bulk_g2s(sbase + st * STAGE_BYTES, nb_g + (long)j * RPS * KD, nbb, mb);
            bulk_g2s(sbase + st * STAGE_BYTES + NB_STAGE_BYTES,
                     tg_g + (long)j * RPS * DD, tgb, mb);
        }
    }

    float* outp = g_partial + ((long)(b * NCHUNK + chunk)) * KD;
    ((float4*)(outp + kl * DD))[d4] = acc0;
    if (has_k1) ((float4*)(outp + (kl + 16) * DD))[d4] = acc1;
}

// Stage 2: one block per (b,k). 256 threads = 16 d4-lanes x 16 groups.
__global__ void __launch_bounds__(256) gat_stage2(float* __restrict__ out)
{
    __shared__ float4 red[16][16];

    const int k = blockIdx.x;              // 0..KK-1
    const int b = blockIdx.y;              // 0..BB-1
    const int tid = threadIdx.x;
    const int d4 = tid & 15;
    const int g  = tid >> 4;               // 0..15

    const float* base = g_partial + ((long)(b * NCHUNK) * KK + k) * DD + d4 * 4;
    const long cstride = (long)KD;

    float4 s = make_float4(0.f, 0.f, 0.f, 0.f);
    #pragma unroll
    for (int j = 0; j < 5; j++) {
        int c = g + j * 16;
        if (c < NCHUNK) {
            float4 v = *(const float4*)(base + (long)c * cstride);
            f4_add(s, v);
        }
    }
    red[g][d4] = s;
    __syncthreads();

    if (tid < 16) {
        float4 S = make_float4(0.f, 0.f, 0.f, 0.f);
        #pragma unroll
        for (int gg = 0; gg < 16; gg++) f4_add(S, red[gg][d4]);

        float4 r;
        r.x = 1.0f / (1.0f + __expf(-S.x));
        r.y = 1.0f / (1.0f + __expf(-S.y));
        r.z = 1.0f / (1.0f + __expf(-S.z));
        r.w = 1.0f / (1.0f + __expf(-S.w));

        ((float4*)(out + ((long)b * KK + k) * DD))[d4] = r;
    }
}

extern "C" void kernel_launch(void* const* d_in, const int* in_sizes, int n_in,
                              void* d_out, int out_size)
{
    const float* targets   = (const float*)d_in[0];
    const float* neighbors = (const float*)d_in[1];
    const float* aw        = (const float*)d_in[2];
    const float* kt        = (const float*)d_in[3];
    const float* bt        = (const float*)d_in[4];
    const float* kn        = (const float*)d_in[5];
    const float* bn        = (const float*)d_in[6];
    float* out             = (float*)d_out;

    (void)in_sizes; (void)n_in; (void)out_size;

    dim3 g1(NCHUNK, BB);
    gat_stage1<<<g1, 256>>>(targets, neighbors, aw, kt, bt, kn, bn);

    dim3 g2(KK, BB);
    gat_stage2<<<g2, 256>>>(out);
}